// round 2
// baseline (speedup 1.0000x reference)
#include <cuda_runtime.h>
#include <math.h>

#define NN 2048
#define BB 8
#define FIN 16
#define TT 12
#define FOUT 32
#define CC 192   // FIN*TT

// Scratch (allocation-free rule: __device__ globals)
__device__ float g_S [(size_t)NN*NN];     // supports
__device__ float g_S2[(size_t)NN*NN];     // 2 * S @ S
__device__ float g_rhs1[(size_t)BB*NN*CC];
__device__ float g_rhs2[(size_t)BB*NN*CC];

// ---------------------------------------------------------------------------
// Kernel 1: S = rowsoftmax(relu(E E^T)).  One block per row n.
// ---------------------------------------------------------------------------
__global__ void __launch_bounds__(256) supports_kernel(const float* __restrict__ E) {
    int n = blockIdx.x;
    __shared__ float en[FIN];
    __shared__ float row[NN];
    __shared__ float red[256];
    int tid = threadIdx.x;
    if (tid < FIN) en[tid] = E[n*FIN + tid];
    __syncthreads();

    float lmax = 0.0f;  // relu => max >= 0
    for (int m = tid; m < NN; m += 256) {
        const float* em = E + m*FIN;
        float s = 0.f;
        #pragma unroll
        for (int f = 0; f < FIN; f++) s = fmaf(en[f], em[f], s);
        s = fmaxf(s, 0.f);
        row[m] = s;
        lmax = fmaxf(lmax, s);
    }
    red[tid] = lmax; __syncthreads();
    for (int s = 128; s > 0; s >>= 1) {
        if (tid < s) red[tid] = fmaxf(red[tid], red[tid+s]);
        __syncthreads();
    }
    float gmax = red[0];
    __syncthreads();

    float lsum = 0.f;
    for (int m = tid; m < NN; m += 256) {
        float e = expf(row[m] - gmax);
        row[m] = e;
        lsum += e;
    }
    red[tid] = lsum; __syncthreads();
    for (int s = 128; s > 0; s >>= 1) {
        if (tid < s) red[tid] += red[tid+s];
        __syncthreads();
    }
    float inv = 1.0f / red[0];
    for (int m = tid; m < NN; m += 256)
        g_S[(size_t)n*NN + m] = row[m] * inv;
}

// ---------------------------------------------------------------------------
// Kernel 2: g_S2 = 2 * S @ S   (2048^3 fp32 GEMM, 128x128x8 tiles, 8x8 micro)
// ---------------------------------------------------------------------------
__global__ void __launch_bounds__(256) s2_gemm_kernel() {
    __shared__ float As[8][128];   // As[k][row]
    __shared__ float Bs[8][128];   // Bs[k][col]
    int tid = threadIdx.x;
    int tx = tid & 15;             // col group
    int ty = tid >> 4;             // row group
    int rowBase = blockIdx.y * 128;
    int colBase = blockIdx.x * 128;

    float acc[8][8];
    #pragma unroll
    for (int i = 0; i < 8; i++)
        #pragma unroll
        for (int j = 0; j < 8; j++) acc[i][j] = 0.f;

    int aRow = tid >> 1;           // 0..127
    int aCol = (tid & 1) * 4;      // 0 or 4
    int bRow = tid >> 5;           // 0..7
    int bCol = (tid & 31) * 4;     // 0..124

    for (int p0 = 0; p0 < NN; p0 += 8) {
        float4 av = *(const float4*)(&g_S[(size_t)(rowBase + aRow)*NN + p0 + aCol]);
        float4 bv = *(const float4*)(&g_S[(size_t)(p0 + bRow)*NN + colBase + bCol]);
        __syncthreads();
        As[aCol+0][aRow] = av.x;
        As[aCol+1][aRow] = av.y;
        As[aCol+2][aRow] = av.z;
        As[aCol+3][aRow] = av.w;
        *(float4*)&Bs[bRow][bCol] = bv;
        __syncthreads();
        #pragma unroll
        for (int k = 0; k < 8; k++) {
            float4 a0 = *(float4*)&As[k][ty*8];
            float4 a1 = *(float4*)&As[k][ty*8 + 4];
            float4 b0 = *(float4*)&Bs[k][tx*8];
            float4 b1 = *(float4*)&Bs[k][tx*8 + 4];
            float ar[8] = {a0.x,a0.y,a0.z,a0.w,a1.x,a1.y,a1.z,a1.w};
            float br[8] = {b0.x,b0.y,b0.z,b0.w,b1.x,b1.y,b1.z,b1.w};
            #pragma unroll
            for (int i = 0; i < 8; i++)
                #pragma unroll
                for (int j = 0; j < 8; j++)
                    acc[i][j] = fmaf(ar[i], br[j], acc[i][j]);
        }
    }
    #pragma unroll
    for (int i = 0; i < 8; i++) {
        size_t off = (size_t)(rowBase + ty*8 + i)*NN + colBase + tx*8;
        float4 v0 = make_float4(2.f*acc[i][0], 2.f*acc[i][1], 2.f*acc[i][2], 2.f*acc[i][3]);
        float4 v1 = make_float4(2.f*acc[i][4], 2.f*acc[i][5], 2.f*acc[i][6], 2.f*acc[i][7]);
        *(float4*)&g_S2[off]     = v0;
        *(float4*)&g_S2[off + 4] = v1;
    }
}

// ---------------------------------------------------------------------------
// Kernel 3: fused dual masked-GEMM.
//   rhs1[b,m,c] = sum_n (S[n,m]   * att[b,n,m]) * x[b,n,c]
//   rhs2[b,m,c] = sum_n (2S2[n,m] * att[b,n,m]) * x[b,n,c]
// BM=64 (m), BN=192 (all c), BK=16, 256 threads, micro 4x12, dual accumulators.
// att is streamed from DRAM exactly once per batch.
// ---------------------------------------------------------------------------
__global__ void __launch_bounds__(256) fused_rhs_kernel(const float* __restrict__ att,
                                                        const float* __restrict__ x) {
    __shared__ float w1s[16][64];
    __shared__ float w2s[16][64];
    __shared__ float xs [16][CC];

    int tid = threadIdx.x;
    int tx = tid & 15;          // c group: c = tx*12 .. +11
    int ty = tid >> 4;          // m group: m = m0 + ty*4 .. +3
    int b  = blockIdx.y;
    int m0 = blockIdx.x * 64;

    const float* attB = att + (size_t)b*NN*NN;
    const float* xB   = x   + (size_t)b*NN*CC;

    float acc1[4][12], acc2[4][12];
    #pragma unroll
    for (int i = 0; i < 4; i++)
        #pragma unroll
        for (int j = 0; j < 12; j++) { acc1[i][j] = 0.f; acc2[i][j] = 0.f; }

    int lk = tid >> 4;          // 0..15 (n within tile)
    int lm = (tid & 15) * 4;    // 0..60 (m within tile)

    for (int n0 = 0; n0 < NN; n0 += 16) {
        size_t wOff = (size_t)(n0 + lk)*NN + m0 + lm;
        float4 av  = *(const float4*)(attB + wOff);
        float4 sv  = *(const float4*)(g_S  + wOff);
        float4 s2v = *(const float4*)(g_S2 + wOff);
        float4 xr[3];
        #pragma unroll
        for (int r = 0; r < 3; r++) {
            int idx = tid + r*256;
            int kk = idx / 48;
            int c4 = (idx % 48) * 4;
            xr[r] = *(const float4*)(xB + (size_t)(n0 + kk)*CC + c4);
        }
        __syncthreads();
        w1s[lk][lm+0] = sv.x*av.x;  w2s[lk][lm+0] = s2v.x*av.x;
        w1s[lk][lm+1] = sv.y*av.y;  w2s[lk][lm+1] = s2v.y*av.y;
        w1s[lk][lm+2] = sv.z*av.z;  w2s[lk][lm+2] = s2v.z*av.z;
        w1s[lk][lm+3] = sv.w*av.w;  w2s[lk][lm+3] = s2v.w*av.w;
        #pragma unroll
        for (int r = 0; r < 3; r++) {
            int idx = tid + r*256;
            int kk = idx / 48;
            int c4 = (idx % 48) * 4;
            *(float4*)&xs[kk][c4] = xr[r];
        }
        __syncthreads();
        #pragma unroll
        for (int kk = 0; kk < 16; kk++) {
            float4 a1v = *(float4*)&w1s[kk][ty*4];
            float4 a2v = *(float4*)&w2s[kk][ty*4];
            float xv[12];
            *(float4*)(xv)     = *(float4*)&xs[kk][tx*12];
            *(float4*)(xv + 4) = *(float4*)&xs[kk][tx*12 + 4];
            *(float4*)(xv + 8) = *(float4*)&xs[kk][tx*12 + 8];
            float a1[4] = {a1v.x, a1v.y, a1v.z, a1v.w};
            float a2[4] = {a2v.x, a2v.y, a2v.z, a2v.w};
            #pragma unroll
            for (int i = 0; i < 4; i++)
                #pragma unroll
                for (int j = 0; j < 12; j++) {
                    acc1[i][j] = fmaf(a1[i], xv[j], acc1[i][j]);
                    acc2[i][j] = fmaf(a2[i], xv[j], acc2[i][j]);
                }
        }
    }
    #pragma unroll
    for (int i = 0; i < 4; i++) {
        size_t off = ((size_t)b*NN + m0 + ty*4 + i)*CC + tx*12;
        #pragma unroll
        for (int q = 0; q < 3; q++) {
            float4 v1 = make_float4(acc1[i][q*4+0], acc1[i][q*4+1], acc1[i][q*4+2], acc1[i][q*4+3]);
            float4 v2 = make_float4(acc2[i][q*4+0], acc2[i][q*4+1], acc2[i][q*4+2], acc2[i][q*4+3]);
            *(float4*)&g_rhs1[off + q*4] = v1;
            *(float4*)&g_rhs2[off + q*4] = v2;
        }
    }
}

// ---------------------------------------------------------------------------
// Kernel 4: epilogue.  One block per (b,m).
//   out[b,m,o,t] = relu( sum_f  rhs1*th1 + rhs2*th2 + d*x[b,m,f,t]*(th0-th2) )
//   where d = att[b,m,m]  (handles k=0 identity and the -I part of T2).
// ---------------------------------------------------------------------------
__global__ void __launch_bounds__(384) epilogue_kernel(const float* __restrict__ att,
                                                       const float* __restrict__ x,
                                                       const float* __restrict__ theta,
                                                       float* __restrict__ out) {
    int bm = blockIdx.x;
    int b = bm >> 11;
    int m = bm & (NN - 1);
    __shared__ float r1[CC], r2[CC], xr[CC];
    __shared__ float ths[3*FIN*FOUT];  // 1536
    int tid = threadIdx.x;  // 384 = 32 o * 12 t
    size_t rowOff = ((size_t)b*NN + m)*CC;
    if (tid < CC) {
        r1[tid] = g_rhs1[rowOff + tid];
        r2[tid] = g_rhs2[rowOff + tid];
        xr[tid] = x[rowOff + tid];
    }
    for (int i = tid; i < 3*FIN*FOUT; i += 384) ths[i] = theta[i];
    __syncthreads();

    float d = att[(size_t)b*NN*NN + (size_t)m*NN + m];
    int o = tid / TT;
    int t = tid - o*TT;
    float acc = 0.f;
    #pragma unroll
    for (int f = 0; f < FIN; f++) {
        float th0 = ths[           f*FOUT + o];
        float th1 = ths[  FIN*FOUT + f*FOUT + o];
        float th2 = ths[2*FIN*FOUT + f*FOUT + o];
        int c = f*TT + t;
        acc = fmaf(r1[c], th1, acc);
        acc = fmaf(r2[c], th2, acc);
        acc = fmaf(d * xr[c], th0 - th2, acc);
    }
    out[(size_t)bm*(FOUT*TT) + tid] = fmaxf(acc, 0.f);
}

// ---------------------------------------------------------------------------
extern "C" void kernel_launch(void* const* d_in, const int* in_sizes, int n_in,
                              void* d_out, int out_size) {
    const float* x = nullptr;
    const float* att = nullptr;
    const float* emb = nullptr;
    const float* theta = nullptr;
    for (int i = 0; i < n_in; i++) {
        switch (in_sizes[i]) {
            case BB*NN*FIN*TT:   x     = (const float*)d_in[i]; break;  // 3145728
            case BB*NN*NN:       att   = (const float*)d_in[i]; break;  // 33554432
            case NN*FIN:         emb   = (const float*)d_in[i]; break;  // 32768
            case 3*FIN*FOUT:     theta = (const float*)d_in[i]; break;  // 1536
            default: break;
        }
    }
    float* out = (float*)d_out;

    supports_kernel<<<NN, 256>>>(emb);
    s2_gemm_kernel<<<dim3(NN/128, NN/128), 256>>>();
    fused_rhs_kernel<<<dim3(NN/64, BB), 256>>>(att, x);
    epilogue_kernel<<<BB*NN, 384>>>(att, x, theta, out);
}

// round 5
// speedup vs baseline: 1.7929x; 1.7929x over previous
#include <cuda_runtime.h>
#include <math.h>

#define NN 2048
#define BB 8
#define FIN 16
#define TT 12
#define FOUT 32
#define CC 192   // FIN*TT

// Scratch (allocation-free rule: __device__ globals)
__device__ float g_S [(size_t)NN*NN];     // supports
__device__ float g_S2[(size_t)NN*NN];     // 2 * S @ S
__device__ float g_rhs1[(size_t)BB*NN*CC];
__device__ float g_rhs2[(size_t)BB*NN*CC];

// ---------------------------------------------------------------------------
// helpers: tf32 rounding + m16n8k8 tf32 MMA
// ---------------------------------------------------------------------------
__device__ __forceinline__ float f2tf32(float x) {
    unsigned r;
    asm("cvt.rna.tf32.f32 %0, %1;" : "=r"(r) : "f"(x));
    return __uint_as_float(r);
}

__device__ __forceinline__ void mma8(float* c,
                                     unsigned a0, unsigned a1, unsigned a2, unsigned a3,
                                     unsigned b0, unsigned b1) {
    asm volatile(
        "mma.sync.aligned.m16n8k8.row.col.f32.tf32.tf32.f32 "
        "{%0,%1,%2,%3},{%4,%5,%6,%7},{%8,%9},{%0,%1,%2,%3};"
        : "+f"(c[0]), "+f"(c[1]), "+f"(c[2]), "+f"(c[3])
        : "r"(a0), "r"(a1), "r"(a2), "r"(a3), "r"(b0), "r"(b1));
}

__device__ __forceinline__ unsigned uldf(const float& f) { return __float_as_uint(f); }

// ---------------------------------------------------------------------------
// Kernel 1: S = rowsoftmax(relu(E E^T)).  One block per row n.
// ---------------------------------------------------------------------------
__global__ void __launch_bounds__(256) supports_kernel(const float* __restrict__ E) {
    int n = blockIdx.x;
    __shared__ float en[FIN];
    __shared__ float row[NN];
    __shared__ float red[256];
    int tid = threadIdx.x;
    if (tid < FIN) en[tid] = E[n*FIN + tid];
    __syncthreads();

    float lmax = 0.0f;  // relu => max >= 0
    for (int m = tid; m < NN; m += 256) {
        const float* em = E + m*FIN;
        float s = 0.f;
        #pragma unroll
        for (int f = 0; f < FIN; f++) s = fmaf(en[f], em[f], s);
        s = fmaxf(s, 0.f);
        row[m] = s;
        lmax = fmaxf(lmax, s);
    }
    red[tid] = lmax; __syncthreads();
    for (int s = 128; s > 0; s >>= 1) {
        if (tid < s) red[tid] = fmaxf(red[tid], red[tid+s]);
        __syncthreads();
    }
    float gmax = red[0];
    __syncthreads();

    float lsum = 0.f;
    for (int m = tid; m < NN; m += 256) {
        float e = expf(row[m] - gmax);
        row[m] = e;
        lsum += e;
    }
    red[tid] = lsum; __syncthreads();
    for (int s = 128; s > 0; s >>= 1) {
        if (tid < s) red[tid] += red[tid+s];
        __syncthreads();
    }
    float inv = 1.0f / red[0];
    for (int m = tid; m < NN; m += 256)
        g_S[(size_t)n*NN + m] = row[m] * inv;
}

// ---------------------------------------------------------------------------
// Kernel 2: g_S2 = 2 * S @ S   (2048^3, TF32 tensor cores)
// Block tile 128x128, 256 threads = 8 warps (2x4), warp tile 64x32, K step 16.
// ---------------------------------------------------------------------------
__global__ void __launch_bounds__(256) s2_gemm_tc() {
    __shared__ float As[16][132];   // As[k][m]
    __shared__ float Bs[16][132];   // Bs[k][n]
    int tid  = threadIdx.x;
    int warp = tid >> 5, lane = tid & 31;
    int wm = warp >> 2;             // 0..1
    int wn = warp & 3;              // 0..3
    int grp = lane >> 2, qid = lane & 3;
    int rowBase = blockIdx.y * 128, colBase = blockIdx.x * 128;

    float acc[4][4][4];
    #pragma unroll
    for (int i = 0; i < 4; i++)
        #pragma unroll
        for (int j = 0; j < 4; j++)
            #pragma unroll
            for (int q = 0; q < 4; q++) acc[i][j][q] = 0.f;

    int ar = tid >> 1;            // 0..127  (m)
    int ac = (tid & 1) * 8;       // 0 or 8  (k)
    int bk = tid >> 4;            // 0..15   (k)
    int bn = (tid & 15) * 4;      // 0..60   (n)

    for (int p0 = 0; p0 < NN; p0 += 16) {
        float4 av0 = *(const float4*)&g_S[(size_t)(rowBase+ar)*NN + p0 + ac];
        float4 av1 = *(const float4*)&g_S[(size_t)(rowBase+ar)*NN + p0 + ac + 4];
        float4 bv0 = *(const float4*)&g_S[(size_t)(p0+bk)*NN + colBase + bn];
        float4 bv1 = *(const float4*)&g_S[(size_t)(p0+bk)*NN + colBase + bn + 64];
        __syncthreads();
        As[ac+0][ar] = f2tf32(av0.x); As[ac+1][ar] = f2tf32(av0.y);
        As[ac+2][ar] = f2tf32(av0.z); As[ac+3][ar] = f2tf32(av0.w);
        As[ac+4][ar] = f2tf32(av1.x); As[ac+5][ar] = f2tf32(av1.y);
        As[ac+6][ar] = f2tf32(av1.z); As[ac+7][ar] = f2tf32(av1.w);
        Bs[bk][bn+0]  = f2tf32(bv0.x); Bs[bk][bn+1]  = f2tf32(bv0.y);
        Bs[bk][bn+2]  = f2tf32(bv0.z); Bs[bk][bn+3]  = f2tf32(bv0.w);
        Bs[bk][bn+64] = f2tf32(bv1.x); Bs[bk][bn+65] = f2tf32(bv1.y);
        Bs[bk][bn+66] = f2tf32(bv1.z); Bs[bk][bn+67] = f2tf32(bv1.w);
        __syncthreads();

        #pragma unroll
        for (int ks = 0; ks < 16; ks += 8) {
            unsigned af[4][4], bf[4][2];
            #pragma unroll
            for (int i = 0; i < 4; i++) {
                int row = wm*64 + i*16 + grp;
                af[i][0] = uldf(As[ks+qid  ][row]);
                af[i][1] = uldf(As[ks+qid  ][row+8]);
                af[i][2] = uldf(As[ks+qid+4][row]);
                af[i][3] = uldf(As[ks+qid+4][row+8]);
            }
            #pragma unroll
            for (int j = 0; j < 4; j++) {
                int col = wn*32 + j*8 + grp;
                bf[j][0] = uldf(Bs[ks+qid  ][col]);
                bf[j][1] = uldf(Bs[ks+qid+4][col]);
            }
            #pragma unroll
            for (int i = 0; i < 4; i++)
                #pragma unroll
                for (int j = 0; j < 4; j++)
                    mma8(acc[i][j], af[i][0], af[i][1], af[i][2], af[i][3],
                         bf[j][0], bf[j][1]);
        }
    }
    #pragma unroll
    for (int i = 0; i < 4; i++) {
        #pragma unroll
        for (int j = 0; j < 4; j++) {
            int r = rowBase + wm*64 + i*16 + grp;
            int c = colBase + wn*32 + j*8 + qid*2;
            float2 v0 = make_float2(2.f*acc[i][j][0], 2.f*acc[i][j][1]);
            float2 v1 = make_float2(2.f*acc[i][j][2], 2.f*acc[i][j][3]);
            *(float2*)&g_S2[(size_t)r*NN + c]     = v0;
            *(float2*)&g_S2[(size_t)(r+8)*NN + c] = v1;
        }
    }
}

// ---------------------------------------------------------------------------
// Kernel 3: fused dual masked-GEMM on TF32 tensor cores.
//   rhs1[b,m,c] = sum_n (S[n,m]   * att[b,n,m]) * x[b,n,c]
//   rhs2[b,m,c] = sum_n (2S2[n,m] * att[b,n,m]) * x[b,n,c]
// Block: M=64 (m), N=192 (c), K step 16 (n). 256 thr = 8 warps (4 m x 2 c),
// warp tile 16x96. att streamed from DRAM exactly once per batch.
// ---------------------------------------------------------------------------
__global__ void __launch_bounds__(256) fused_rhs_tc(const float* __restrict__ att,
                                                    const float* __restrict__ x) {
    __shared__ float W1s[16][68];   // [n][m] weight 1
    __shared__ float W2s[16][68];   // [n][m] weight 2
    __shared__ float Xs [16][196];  // [n][c]

    int tid  = threadIdx.x;
    int warp = tid >> 5, lane = tid & 31;
    int wm = warp >> 1;             // 0..3
    int wn = warp & 1;              // 0..1
    int grp = lane >> 2, qid = lane & 3;
    int b  = blockIdx.y;
    int m0 = blockIdx.x * 64;

    const float* attB = att + (size_t)b*NN*NN;
    const float* xB   = x   + (size_t)b*NN*CC;

    float acc1[12][4], acc2[12][4];
    #pragma unroll
    for (int j = 0; j < 12; j++)
        #pragma unroll
        for (int q = 0; q < 4; q++) { acc1[j][q] = 0.f; acc2[j][q] = 0.f; }

    int lk = tid >> 4;          // 0..15 (n within tile)
    int lm = (tid & 15) * 4;    // 0..60 (m within tile)

    for (int n0 = 0; n0 < NN; n0 += 16) {
        size_t wOff = (size_t)(n0 + lk)*NN + m0 + lm;
        float4 av  = *(const float4*)(attB + wOff);
        float4 sv  = *(const float4*)(g_S  + wOff);
        float4 s2v = *(const float4*)(g_S2 + wOff);
        float4 xr[3];
        #pragma unroll
        for (int r = 0; r < 3; r++) {
            int idx = tid + r*256;
            int kk = idx / 48;
            int c4 = (idx % 48) * 4;
            xr[r] = *(const float4*)(xB + (size_t)(n0 + kk)*CC + c4);
        }
        __syncthreads();
        W1s[lk][lm+0] = f2tf32(sv.x*av.x);  W2s[lk][lm+0] = f2tf32(s2v.x*av.x);
        W1s[lk][lm+1] = f2tf32(sv.y*av.y);  W2s[lk][lm+1] = f2tf32(s2v.y*av.y);
        W1s[lk][lm+2] = f2tf32(sv.z*av.z);  W2s[lk][lm+2] = f2tf32(s2v.z*av.z);
        W1s[lk][lm+3] = f2tf32(sv.w*av.w);  W2s[lk][lm+3] = f2tf32(s2v.w*av.w);
        #pragma unroll
        for (int r = 0; r < 3; r++) {
            int idx = tid + r*256;
            int kk = idx / 48;
            int c4 = (idx % 48) * 4;
            Xs[kk][c4+0] = f2tf32(xr[r].x);
            Xs[kk][c4+1] = f2tf32(xr[r].y);
            Xs[kk][c4+2] = f2tf32(xr[r].z);
            Xs[kk][c4+3] = f2tf32(xr[r].w);
        }
        __syncthreads();

        #pragma unroll
        for (int ks = 0; ks < 16; ks += 8) {
            unsigned a1f[4], a2f[4];
            int row = wm*16 + grp;
            a1f[0] = uldf(W1s[ks+qid  ][row]);
            a1f[1] = uldf(W1s[ks+qid  ][row+8]);
            a1f[2] = uldf(W1s[ks+qid+4][row]);
            a1f[3] = uldf(W1s[ks+qid+4][row+8]);
            a2f[0] = uldf(W2s[ks+qid  ][row]);
            a2f[1] = uldf(W2s[ks+qid  ][row+8]);
            a2f[2] = uldf(W2s[ks+qid+4][row]);
            a2f[3] = uldf(W2s[ks+qid+4][row+8]);
            #pragma unroll
            for (int j = 0; j < 12; j++) {
                int col = wn*96 + j*8 + grp;
                unsigned b0 = uldf(Xs[ks+qid  ][col]);
                unsigned b1 = uldf(Xs[ks+qid+4][col]);
                mma8(acc1[j], a1f[0], a1f[1], a1f[2], a1f[3], b0, b1);
                mma8(acc2[j], a2f[0], a2f[1], a2f[2], a2f[3], b0, b1);
            }
        }
    }
    // store
    #pragma unroll
    for (int j = 0; j < 12; j++) {
        int r = m0 + wm*16 + grp;
        int c = wn*96 + j*8 + qid*2;
        size_t base = ((size_t)b*NN + r)*CC + c;
        *(float2*)&g_rhs1[base]          = make_float2(acc1[j][0], acc1[j][1]);
        *(float2*)&g_rhs1[base + 8*CC]   = make_float2(acc1[j][2], acc1[j][3]);
        *(float2*)&g_rhs2[base]          = make_float2(acc2[j][0], acc2[j][1]);
        *(float2*)&g_rhs2[base + 8*CC]   = make_float2(acc2[j][2], acc2[j][3]);
    }
}

// ---------------------------------------------------------------------------
// Kernel 4: epilogue v2.  Block = 16 (b,m) rows, 384 threads = (o,t) grid.
//   out[b,m,o,t] = relu( sum_f rhs1*th1 + rhs2*th2 + d*x[b,m,f,t]*(th0-th2) )
// theta hoisted to registers; flat float4 staging of rhs1/rhs2/x rows.
// ---------------------------------------------------------------------------
#define EROWS 16
__global__ void __launch_bounds__(384) epilogue2_kernel(const float* __restrict__ att,
                                                        const float* __restrict__ x,
                                                        const float* __restrict__ theta,
                                                        float* __restrict__ out) {
    __shared__ float r1[EROWS*CC], r2[EROWS*CC], xs[EROWS*CC];
    __shared__ float ds[EROWS];
    int blk = blockIdx.x;                 // 1024 blocks
    int tid = threadIdx.x;
    size_t base = (size_t)blk * EROWS * CC;

    #pragma unroll
    for (int r = 0; r < 2; r++) {
        int idx = tid + r*384;            // 0..767 float4s
        *(float4*)&r1[idx*4] = *(const float4*)&g_rhs1[base + (size_t)idx*4];
        *(float4*)&r2[idx*4] = *(const float4*)&g_rhs2[base + (size_t)idx*4];
        *(float4*)&xs[idx*4] = *(const float4*)&x[base + (size_t)idx*4];
    }
    if (tid < EROWS) {
        int bm = blk*EROWS + tid;
        int b = bm >> 11;
        int m = bm & (NN - 1);
        ds[tid] = att[(size_t)b*NN*NN + (size_t)m*NN + m];
    }
    int o = tid / TT;
    int t = tid - o*TT;
    float th1[FIN], th2[FIN], th0m2[FIN];
    #pragma unroll
    for (int f = 0; f < FIN; f++) {
        float t0 = theta[              f*FOUT + o];
        float t1 = theta[  FIN*FOUT + f*FOUT + o];
        float t2 = theta[2*FIN*FOUT + f*FOUT + o];
        th1[f] = t1; th2[f] = t2; th0m2[f] = t0 - t2;
    }
    __syncthreads();

    size_t outBase = (size_t)blk * EROWS * (FOUT*TT);
    #pragma unroll 4
    for (int row = 0; row < EROWS; row++) {
        float d = ds[row];
        const float* R1 = r1 + row*CC;
        const float* R2 = r2 + row*CC;
        const float* X  = xs + row*CC;
        float acc = 0.f;
        #pragma unroll
        for (int f = 0; f < FIN; f++) {
            int c = f*TT + t;
            acc = fmaf(R1[c], th1[f], acc);
            acc = fmaf(R2[c], th2[f], acc);
            acc = fmaf(d * X[c], th0m2[f], acc);
        }
        out[outBase + row*(FOUT*TT) + tid] = fmaxf(acc, 0.f);
    }
}

// ---------------------------------------------------------------------------
extern "C" void kernel_launch(void* const* d_in, const int* in_sizes, int n_in,
                              void* d_out, int out_size) {
    const float* x = nullptr;
    const float* att = nullptr;
    const float* emb = nullptr;
    const float* theta = nullptr;
    for (int i = 0; i < n_in; i++) {
        switch (in_sizes[i]) {
            case BB*NN*FIN*TT:   x     = (const float*)d_in[i]; break;  // 3145728
            case BB*NN*NN:       att   = (const float*)d_in[i]; break;  // 33554432
            case NN*FIN:         emb   = (const float*)d_in[i]; break;  // 32768
            case 3*FIN*FOUT:     theta = (const float*)d_in[i]; break;  // 1536
            default: break;
        }
    }
    float* out = (float*)d_out;

    supports_kernel<<<NN, 256>>>(emb);
    s2_gemm_tc<<<dim3(NN/128, NN/128), 256>>>();
    fused_rhs_tc<<<dim3(NN/64, BB), 256>>>(att, x);
    epilogue2_kernel<<<BB*NN/EROWS, 384>>>(att, x, theta, out);
}

// round 6
// speedup vs baseline: 1.8554x; 1.0349x over previous
#include <cuda_runtime.h>
#include <math.h>

#define NN 2048
#define BB 8
#define FIN 16
#define TT 12
#define FOUT 32
#define CC 192   // FIN*TT

// Scratch (allocation-free rule: __device__ globals)
__device__ float g_S  [(size_t)NN*NN];     // supports (tf32-rounded)
__device__ float g_S2 [(size_t)NN*NN];     // 2 * S @ S (tf32-rounded)
__device__ float g_xtf[(size_t)BB*NN*CC];  // x tf32-rounded
__device__ float g_rhs1[(size_t)BB*NN*CC];
__device__ float g_rhs2[(size_t)BB*NN*CC];

// ---------------------------------------------------------------------------
// helpers
// ---------------------------------------------------------------------------
__device__ __forceinline__ float f2tf32(float x) {
    unsigned r;
    asm("cvt.rna.tf32.f32 %0, %1;" : "=r"(r) : "f"(x));
    return __uint_as_float(r);
}
__device__ __forceinline__ void mma8(float* c,
                                     unsigned a0, unsigned a1, unsigned a2, unsigned a3,
                                     unsigned b0, unsigned b1) {
    asm volatile(
        "mma.sync.aligned.m16n8k8.row.col.f32.tf32.tf32.f32 "
        "{%0,%1,%2,%3},{%4,%5,%6,%7},{%8,%9},{%0,%1,%2,%3};"
        : "+f"(c[0]), "+f"(c[1]), "+f"(c[2]), "+f"(c[3])
        : "r"(a0), "r"(a1), "r"(a2), "r"(a3), "r"(b0), "r"(b1));
}
__device__ __forceinline__ unsigned uldf(const float& f) { return __float_as_uint(f); }

__device__ __forceinline__ void cpa16(unsigned saddr, const void* gptr) {
    asm volatile("cp.async.cg.shared.global [%0], [%1], 16;" :: "r"(saddr), "l"(gptr));
}
__device__ __forceinline__ void cpa_commit() {
    asm volatile("cp.async.commit_group;" ::: "memory");
}
template<int N> __device__ __forceinline__ void cpa_wait() {
    asm volatile("cp.async.wait_group %0;" :: "n"(N) : "memory");
}

// ---------------------------------------------------------------------------
// Kernel 1: S = rowsoftmax(relu(E E^T)), stored tf32-rounded.
// ---------------------------------------------------------------------------
__global__ void __launch_bounds__(256) supports_kernel(const float* __restrict__ E) {
    int n = blockIdx.x;
    __shared__ float en[FIN];
    __shared__ float row[NN];
    __shared__ float red[256];
    int tid = threadIdx.x;
    if (tid < FIN) en[tid] = E[n*FIN + tid];
    __syncthreads();

    float lmax = 0.0f;
    for (int m = tid; m < NN; m += 256) {
        const float* em = E + m*FIN;
        float s = 0.f;
        #pragma unroll
        for (int f = 0; f < FIN; f++) s = fmaf(en[f], em[f], s);
        s = fmaxf(s, 0.f);
        row[m] = s;
        lmax = fmaxf(lmax, s);
    }
    red[tid] = lmax; __syncthreads();
    for (int s = 128; s > 0; s >>= 1) {
        if (tid < s) red[tid] = fmaxf(red[tid], red[tid+s]);
        __syncthreads();
    }
    float gmax = red[0];
    __syncthreads();

    float lsum = 0.f;
    for (int m = tid; m < NN; m += 256) {
        float e = expf(row[m] - gmax);
        row[m] = e;
        lsum += e;
    }
    red[tid] = lsum; __syncthreads();
    for (int s = 128; s > 0; s >>= 1) {
        if (tid < s) red[tid] += red[tid+s];
        __syncthreads();
    }
    float inv = 1.0f / red[0];
    for (int m = tid; m < NN; m += 256)
        g_S[(size_t)n*NN + m] = f2tf32(row[m] * inv);
}

// ---------------------------------------------------------------------------
// Kernel 1b: pre-round x to tf32 (so fused kernel needs no inner cvt on B).
// ---------------------------------------------------------------------------
__global__ void __launch_bounds__(256) xtf_kernel(const float* __restrict__ x) {
    int i = blockIdx.x * 256 + threadIdx.x;   // over float4s: BB*NN*CC/4 = 786432
    float4 v = ((const float4*)x)[i];
    v.x = f2tf32(v.x); v.y = f2tf32(v.y); v.z = f2tf32(v.z); v.w = f2tf32(v.w);
    ((float4*)g_xtf)[i] = v;
}

// ---------------------------------------------------------------------------
// Kernel 2: g_S2 = 2 * S @ S   (2048^3 TF32, cp.async 2-stage pipeline)
// Block 128x128, 256 thr = 8 warps (2m x 4n), warp 64x32, K-tile 16.
// As[m][k] stride 20, Bs[k][n] stride 136 -> conflict-free fragment LDS.
// ---------------------------------------------------------------------------
__global__ void __launch_bounds__(256) s2_gemm_tc2() {
    __shared__ __align__(16) float As[2][128][20];
    __shared__ __align__(16) float Bs[2][16][136];
    int tid  = threadIdx.x;
    int warp = tid >> 5, lane = tid & 31;
    int wm = warp >> 2, wn = warp & 3;
    int grp = lane >> 2, qid = lane & 3;
    int rowBase = blockIdx.y * 128, colBase = blockIdx.x * 128;

    float acc[4][4][4];
    #pragma unroll
    for (int i = 0; i < 4; i++)
        #pragma unroll
        for (int j = 0; j < 4; j++)
            #pragma unroll
            for (int q = 0; q < 4; q++) acc[i][j][q] = 0.f;

    // cp.async assignments: A 512 chunks, B 512 chunks, 2+2 per thread
    int aRow0 = (tid*2) >> 2,      aCk0 = (tid*2) & 3;
    int aRow1 = (tid*2+1) >> 2,    aCk1 = (tid*2+1) & 3;
    int bRow0 = (tid*2) >> 5,      bCn0 = (tid*2) & 31;
    int bRow1 = (tid*2+1) >> 5,    bCn1 = (tid*2+1) & 31;

#define S2_LOAD(st, p0)                                                              \
    do {                                                                             \
        cpa16((unsigned)__cvta_generic_to_shared(&As[st][aRow0][aCk0*4]),            \
              &g_S[(size_t)(rowBase+aRow0)*NN + (p0) + aCk0*4]);                     \
        cpa16((unsigned)__cvta_generic_to_shared(&As[st][aRow1][aCk1*4]),            \
              &g_S[(size_t)(rowBase+aRow1)*NN + (p0) + aCk1*4]);                     \
        cpa16((unsigned)__cvta_generic_to_shared(&Bs[st][bRow0][bCn0*4]),            \
              &g_S[(size_t)((p0)+bRow0)*NN + colBase + bCn0*4]);                     \
        cpa16((unsigned)__cvta_generic_to_shared(&Bs[st][bRow1][bCn1*4]),            \
              &g_S[(size_t)((p0)+bRow1)*NN + colBase + bCn1*4]);                     \
    } while (0)

    S2_LOAD(0, 0);
    cpa_commit();

    for (int it = 0; it < NN/16; it++) {
        int cur = it & 1;
        if (it < NN/16 - 1) S2_LOAD(cur ^ 1, (it + 1) * 16);
        cpa_commit();
        cpa_wait<1>();
        __syncthreads();

        #pragma unroll
        for (int ks = 0; ks < 16; ks += 8) {
            unsigned af[4][4], bf[4][2];
            #pragma unroll
            for (int i = 0; i < 4; i++) {
                int row = wm*64 + i*16 + grp;
                af[i][0] = uldf(As[cur][row  ][ks+qid  ]);
                af[i][1] = uldf(As[cur][row+8][ks+qid  ]);
                af[i][2] = uldf(As[cur][row  ][ks+qid+4]);
                af[i][3] = uldf(As[cur][row+8][ks+qid+4]);
            }
            #pragma unroll
            for (int j = 0; j < 4; j++) {
                int col = wn*32 + j*8 + grp;
                bf[j][0] = uldf(Bs[cur][ks+qid  ][col]);
                bf[j][1] = uldf(Bs[cur][ks+qid+4][col]);
            }
            #pragma unroll
            for (int i = 0; i < 4; i++)
                #pragma unroll
                for (int j = 0; j < 4; j++)
                    mma8(acc[i][j], af[i][0], af[i][1], af[i][2], af[i][3],
                         bf[j][0], bf[j][1]);
        }
        __syncthreads();
    }
#undef S2_LOAD

    #pragma unroll
    for (int i = 0; i < 4; i++) {
        #pragma unroll
        for (int j = 0; j < 4; j++) {
            int r = rowBase + wm*64 + i*16 + grp;
            int c = colBase + wn*32 + j*8 + qid*2;
            float2 v0 = make_float2(f2tf32(2.f*acc[i][j][0]), f2tf32(2.f*acc[i][j][1]));
            float2 v1 = make_float2(f2tf32(2.f*acc[i][j][2]), f2tf32(2.f*acc[i][j][3]));
            *(float2*)&g_S2[(size_t)r*NN + c]     = v0;
            *(float2*)&g_S2[(size_t)(r+8)*NN + c] = v1;
        }
    }
}

// ---------------------------------------------------------------------------
// Kernel 3: fused dual masked-GEMM, cp.async 2-stage pipeline.
//   rhs1[b,m,c] = sum_n (S[n,m]   * att[b,n,m]) * x[b,n,c]
//   rhs2[b,m,c] = sum_n (2S2[n,m] * att[b,n,m]) * x[b,n,c]
// Block 32m x 192c, 128 thr = 4 warps (2m x 2c), warp 16x96, K-tile 16 (n).
// Mask multiply happens in A-fragment registers (S,S2,att loaded raw).
// att streamed from DRAM exactly once. Ts stride 40, Xs stride 200 (no conflicts).
// ---------------------------------------------------------------------------
__global__ void __launch_bounds__(128) fused_rhs_tc2(const float* __restrict__ att) {
    __shared__ __align__(16) float Ts[2][3][16][40];   // 0=S, 1=S2, 2=att : [n][m]
    __shared__ __align__(16) float Xs[2][16][200];     // [n][c]

    int tid  = threadIdx.x;
    int warp = tid >> 5, lane = tid & 31;
    int wm = warp >> 1, wn = warp & 1;
    int grp = lane >> 2, qid = lane & 3;
    int b  = blockIdx.y;
    int m0 = blockIdx.x * 32;

    const float* attB = att   + (size_t)b*NN*NN;
    const float* xB   = g_xtf + (size_t)b*NN*CC;

    float acc1[12][4], acc2[12][4];
    #pragma unroll
    for (int j = 0; j < 12; j++)
        #pragma unroll
        for (int q = 0; q < 4; q++) { acc1[j][q] = 0.f; acc2[j][q] = 0.f; }

    // cp.async assignments: A-side 3 mats x 128 chunks = 384 (3/thr), X 768 (6/thr)
    // A chunk ca: mat = ca>>7, row = (ca>>3)&15, cm = ca&7
    // X chunk cx: row = cx/48, cc = cx%48

#define F_LOAD(st, n0)                                                                 \
    do {                                                                               \
        _Pragma("unroll")                                                              \
        for (int r = 0; r < 3; r++) {                                                  \
            int ca = tid*3 + r;                                                        \
            int mat = ca >> 7, rem = ca & 127;                                         \
            int row = rem >> 3, cm = rem & 7;                                          \
            const float* src = (mat == 0) ? g_S : (mat == 1) ? g_S2 : attB;            \
            cpa16((unsigned)__cvta_generic_to_shared(&Ts[st][mat][row][cm*4]),         \
                  src + (size_t)((n0)+row)*NN + m0 + cm*4);                            \
        }                                                                              \
        _Pragma("unroll")                                                              \
        for (int r = 0; r < 6; r++) {                                                  \
            int cx = tid*6 + r;                                                        \
            int row = cx / 48, cc = cx % 48;                                           \
            cpa16((unsigned)__cvta_generic_to_shared(&Xs[st][row][cc*4]),              \
                  xB + (size_t)((n0)+row)*CC + cc*4);                                  \
        }                                                                              \
    } while (0)

    F_LOAD(0, 0);
    cpa_commit();

    for (int it = 0; it < NN/16; it++) {
        int cur = it & 1;
        if (it < NN/16 - 1) F_LOAD(cur ^ 1, (it + 1) * 16);
        cpa_commit();
        cpa_wait<1>();
        __syncthreads();

        #pragma unroll
        for (int ks = 0; ks < 16; ks += 8) {
            int row = wm*16 + grp;
            float s0  = Ts[cur][0][ks+qid  ][row],  s1  = Ts[cur][0][ks+qid  ][row+8];
            float s2_ = Ts[cur][0][ks+qid+4][row],  s3  = Ts[cur][0][ks+qid+4][row+8];
            float u0  = Ts[cur][1][ks+qid  ][row],  u1  = Ts[cur][1][ks+qid  ][row+8];
            float u2  = Ts[cur][1][ks+qid+4][row],  u3  = Ts[cur][1][ks+qid+4][row+8];
            float a0  = Ts[cur][2][ks+qid  ][row],  a1  = Ts[cur][2][ks+qid  ][row+8];
            float a2  = Ts[cur][2][ks+qid+4][row],  a3  = Ts[cur][2][ks+qid+4][row+8];
            unsigned w1f[4], w2f[4];
            w1f[0] = uldf(f2tf32(s0 *a0)); w1f[1] = uldf(f2tf32(s1 *a1));
            w1f[2] = uldf(f2tf32(s2_*a2)); w1f[3] = uldf(f2tf32(s3 *a3));
            w2f[0] = uldf(f2tf32(u0 *a0)); w2f[1] = uldf(f2tf32(u1 *a1));
            w2f[2] = uldf(f2tf32(u2 *a2)); w2f[3] = uldf(f2tf32(u3 *a3));
            #pragma unroll
            for (int j = 0; j < 12; j++) {
                int col = wn*96 + j*8 + grp;
                unsigned b0 = uldf(Xs[cur][ks+qid  ][col]);
                unsigned b1 = uldf(Xs[cur][ks+qid+4][col]);
                mma8(acc1[j], w1f[0], w1f[1], w1f[2], w1f[3], b0, b1);
                mma8(acc2[j], w2f[0], w2f[1], w2f[2], w2f[3], b0, b1);
            }
        }
        __syncthreads();
    }
#undef F_LOAD

    #pragma unroll
    for (int j = 0; j < 12; j++) {
        int r = m0 + wm*16 + grp;
        int c = wn*96 + j*8 + qid*2;
        size_t base = ((size_t)b*NN + r)*CC + c;
        *(float2*)&g_rhs1[base]        = make_float2(acc1[j][0], acc1[j][1]);
        *(float2*)&g_rhs1[base + 8*CC] = make_float2(acc1[j][2], acc1[j][3]);
        *(float2*)&g_rhs2[base]        = make_float2(acc2[j][0], acc2[j][1]);
        *(float2*)&g_rhs2[base + 8*CC] = make_float2(acc2[j][2], acc2[j][3]);
    }
}

// ---------------------------------------------------------------------------
// Kernel 4: epilogue (unchanged from R5).
// ---------------------------------------------------------------------------
#define EROWS 16
__global__ void __launch_bounds__(384) epilogue2_kernel(const float* __restrict__ att,
                                                        const float* __restrict__ x,
                                                        const float* __restrict__ theta,
                                                        float* __restrict__ out) {
    __shared__ float r1[EROWS*CC], r2[EROWS*CC], xs[EROWS*CC];
    __shared__ float ds[EROWS];
    int blk = blockIdx.x;
    int tid = threadIdx.x;
    size_t base = (size_t)blk * EROWS * CC;

    #pragma unroll
    for (int r = 0; r < 2; r++) {
        int idx = tid + r*384;
        *(float4*)&r1[idx*4] = *(const float4*)&g_rhs1[base + (size_t)idx*4];
        *(float4*)&r2[idx*4] = *(const float4*)&g_rhs2[base + (size_t)idx*4];
        *(float4*)&xs[idx*4] = *(const float4*)&x[base + (size_t)idx*4];
    }
    if (tid < EROWS) {
        int bm = blk*EROWS + tid;
        int b = bm >> 11;
        int m = bm & (NN - 1);
        ds[tid] = att[(size_t)b*NN*NN + (size_t)m*NN + m];
    }
    int o = tid / TT;
    int t = tid - o*TT;
    float th1[FIN], th2[FIN], th0m2[FIN];
    #pragma unroll
    for (int f = 0; f < FIN; f++) {
        float t0 = theta[              f*FOUT + o];
        float t1 = theta[  FIN*FOUT + f*FOUT + o];
        float t2 = theta[2*FIN*FOUT + f*FOUT + o];
        th1[f] = t1; th2[f] = t2; th0m2[f] = t0 - t2;
    }
    __syncthreads();

    size_t outBase = (size_t)blk * EROWS * (FOUT*TT);
    #pragma unroll 4
    for (int row = 0; row < EROWS; row++) {
        float d = ds[row];
        const float* R1 = r1 + row*CC;
        const float* R2 = r2 + row*CC;
        const float* X  = xs + row*CC;
        float acc = 0.f;
        #pragma unroll
        for (int f = 0; f < FIN; f++) {
            int c = f*TT + t;
            acc = fmaf(R1[c], th1[f], acc);
            acc = fmaf(R2[c], th2[f], acc);
            acc = fmaf(d * X[c], th0m2[f], acc);
        }
        out[outBase + row*(FOUT*TT) + tid] = fmaxf(acc, 0.f);
    }
}

// ---------------------------------------------------------------------------
extern "C" void kernel_launch(void* const* d_in, const int* in_sizes, int n_in,
                              void* d_out, int out_size) {
    const float* x = nullptr;
    const float* att = nullptr;
    const float* emb = nullptr;
    const float* theta = nullptr;
    for (int i = 0; i < n_in; i++) {
        switch (in_sizes[i]) {
            case BB*NN*FIN*TT:   x     = (const float*)d_in[i]; break;
            case BB*NN*NN:       att   = (const float*)d_in[i]; break;
            case NN*FIN:         emb   = (const float*)d_in[i]; break;
            case 3*FIN*FOUT:     theta = (const float*)d_in[i]; break;
            default: break;
        }
    }
    float* out = (float*)d_out;

    supports_kernel<<<NN, 256>>>(emb);
    xtf_kernel<<<BB*NN*CC/4/256, 256>>>(x);
    s2_gemm_tc2<<<dim3(NN/128, NN/128), 256>>>();
    fused_rhs_tc2<<<dim3(NN/32, BB), 128>>>(att);
    epilogue2_kernel<<<BB*NN/EROWS, 384>>>(att, x, theta, out);
}